// round 16
// baseline (speedup 1.0000x reference)
#include <cuda_runtime.h>
#include <cuda_fp16.h>
#include <cstdint>
#include <math.h>

#define RNG_PARTITIONABLE 1   // confirmed passing config -- do not change

constexpr int BATCH = 4, SEQ = 1024, DM = 1024, NH = 16, DK = 64, DFF = 4096;
constexpr int NSAMP = 35;
constexpr int NTOP  = 35;
constexpr int ROWS  = BATCH * SEQ;
constexpr size_t NELEM = (size_t)ROWS * DM;

// ---------------------------------------------------------------------------
// Static device scratch
// ---------------------------------------------------------------------------
__device__ float g_q[NELEM];
__device__ float g_k[NELEM];
__device__ float g_v[NELEM];
__device__ float g_xin[NELEM];
__device__ float g_x1[NELEM];
__device__ float g_x2[NELEM];
__device__ float g_M[BATCH * NH * SEQ];
__device__ int   g_top[BATCH * NH * NTOP];
__device__ float g_mu[DM];
__device__ float g_rstd[DM];
__device__ float g_psum[64 * DM];
__device__ float g_psq[64 * DM];
// fp16 buffers
__device__ __half g_htgt[NELEM];
__device__ __half g_hmem[NELEM];
__device__ __half g_hx1[NELEM];
__device__ __half g_hx2[NELEM];
__device__ __half g_hctx[NELEM];
__device__ __half g_hh[(size_t)ROWS * DFF];
__device__ __half g_hwq[DM * DM];
__device__ __half g_hwk[DM * DM];
__device__ __half g_hwv[DM * DM];
__device__ __half g_hwo[DM * DM];
__device__ __half g_hw1[(size_t)DM * DFF];
__device__ __half g_hw2[(size_t)DM * DFF];

// ---------------------------------------------------------------------------
// Helpers
// ---------------------------------------------------------------------------
__device__ __forceinline__ float tf32r(float x) {
    uint32_t u;
    asm("cvt.rna.tf32.f32 %0, %1;" : "=r"(u) : "f"(x));
    return __uint_as_float(u);
}

__device__ __forceinline__ uint32_t saddr(const void* p) {
    return (uint32_t)__cvta_generic_to_shared(p);
}

__device__ __forceinline__ void cp16(uint32_t dst, const void* src) {
    asm volatile("cp.async.cg.shared.global [%0], [%1], 16;" :: "r"(dst), "l"(src));
}

#define LDSM_X4(r0, r1, r2, r3, a) \
    asm volatile("ldmatrix.sync.aligned.m8n8.x4.shared.b16 {%0,%1,%2,%3}, [%4];" \
                 : "=r"(r0), "=r"(r1), "=r"(r2), "=r"(r3) : "r"(a))

#define LDSM_X4_T(r0, r1, r2, r3, a) \
    asm volatile("ldmatrix.sync.aligned.m8n8.x4.trans.shared.b16 {%0,%1,%2,%3}, [%4];" \
                 : "=r"(r0), "=r"(r1), "=r"(r2), "=r"(r3) : "r"(a))

__device__ __forceinline__ void mma_f16(float c[4], uint32_t a0, uint32_t a1,
                                        uint32_t a2, uint32_t a3,
                                        uint32_t b0, uint32_t b1) {
    asm volatile(
        "mma.sync.aligned.m16n8k16.row.col.f32.f16.f16.f32 "
        "{%0,%1,%2,%3}, {%4,%5,%6,%7}, {%8,%9}, {%0,%1,%2,%3};"
        : "+f"(c[0]), "+f"(c[1]), "+f"(c[2]), "+f"(c[3])
        : "r"(a0), "r"(a1), "r"(a2), "r"(a3), "r"(b0), "r"(b1));
}

// ---------------------------------------------------------------------------
// threefry2x32 (frozen)
// ---------------------------------------------------------------------------
__host__ __device__ __forceinline__ void tf2x32(uint32_t k0, uint32_t k1,
                                                uint32_t x0, uint32_t x1,
                                                uint32_t &o0, uint32_t &o1) {
    uint32_t ks2 = k0 ^ k1 ^ 0x1BD11BDAu;
    x0 += k0; x1 += k1;
#define TF_R(r) { x0 += x1; x1 = (x1 << (r)) | (x1 >> (32 - (r))); x1 ^= x0; }
    TF_R(13) TF_R(15) TF_R(26) TF_R(6)
    x0 += k1; x1 += ks2 + 1u;
    TF_R(17) TF_R(29) TF_R(16) TF_R(24)
    x0 += ks2; x1 += k0 + 2u;
    TF_R(13) TF_R(15) TF_R(26) TF_R(6)
    x0 += k0; x1 += k1 + 3u;
    TF_R(17) TF_R(29) TF_R(16) TF_R(24)
    x0 += k1; x1 += ks2 + 4u;
    TF_R(13) TF_R(15) TF_R(26) TF_R(6)
    x0 += ks2; x1 += k0 + 5u;
#undef TF_R
    o0 = x0; o1 = x1;
}

// device-side randint draw: sample s of row l  ->  idx = bits(l*35+s) & 1023
__device__ __forceinline__ int draw_idx(uint32_t ka, uint32_t kb, uint32_t j) {
#if RNG_PARTITIONABLE
    uint32_t o0, o1;
    tf2x32(ka, kb, 0u, j, o0, o1);
    return (int)((o0 ^ o1) & 1023u);
#else
    constexpr uint32_t HALF = (uint32_t)(SEQ * NSAMP / 2);
    uint32_t o0, o1;
    if (j < HALF) {
        tf2x32(ka, kb, j, HALF + j, o0, o1);
        return (int)(o0 & 1023u);
    } else {
        tf2x32(ka, kb, j - HALF, j, o0, o1);
        return (int)(o1 & 1023u);
    }
#endif
}

// ---------------------------------------------------------------------------
// f32 -> f16 conversion (RN), vectorized
// ---------------------------------------------------------------------------
__global__ void f2h_kernel(const float* __restrict__ x, __half* __restrict__ y) {
    size_t i = (size_t)blockIdx.x * 256 + threadIdx.x;
    float4 v = ((const float4*)x)[i];
    __half2 h0 = __floats2half2_rn(v.x, v.y);
    __half2 h1 = __floats2half2_rn(v.z, v.w);
    uint2 o = { *(uint32_t*)&h0, *(uint32_t*)&h1 };
    ((uint2*)y)[i] = o;
}

static void run_f2h(const float* x, __half* y, size_t n) {
    f2h_kernel<<<(int)(n / 4 / 256), 256>>>(x, y);
}

// ---------------------------------------------------------------------------
// FP16 tensor-core GEMM: 128x128x32 tiles, 3-stage cp.async (measured best)
// ---------------------------------------------------------------------------
constexpr int HA_ST = 10240;
constexpr int HB_ST = 8704;
constexpr int H_SMEM = 3 * (HA_ST + HB_ST);

__device__ __forceinline__ void gemm_h_body(const __half* __restrict__ A,
                                            const __half* __restrict__ B,
                                            const float* __restrict__ bias,
                                            const float* __restrict__ resid,
                                            float* __restrict__ C,
                                            __half* __restrict__ Ch,
                                            int M, int N, int K, int act, char* smem) {
    uint32_t sb = saddr(smem);
    const int tid = threadIdx.x;
    const int lane = tid & 31, warp = tid >> 5;
    const int warpM = warp >> 2, warpN = warp & 3;
    const int grp = lane >> 2, thr = lane & 3;
    const int row0 = blockIdx.y * 128, col0 = blockIdx.x * 128;
    const int T = K / 32;

    float acc[4][4][4];
#pragma unroll
    for (int mt = 0; mt < 4; mt++)
#pragma unroll
        for (int nt = 0; nt < 4; nt++)
#pragma unroll
            for (int i = 0; i < 4; i++) acc[mt][nt][i] = 0.0f;

    auto issue = [&](int t) {
        int s = t % 3;
        uint32_t ab = sb + s * HA_ST;
        uint32_t bb = sb + 3 * HA_ST + s * HB_ST;
#pragma unroll
        for (int i = 0; i < 2; i++) {
            int f = tid + i * 256;
            int ar = f >> 2, ac = f & 3;
            cp16(ab + ar * 80 + ac * 16, &A[(size_t)(row0 + ar) * K + t * 32 + ac * 8]);
            int br = f >> 4, bc = f & 15;
            cp16(bb + br * 272 + bc * 16, &B[(size_t)(t * 32 + br) * N + col0 + bc * 8]);
        }
        asm volatile("cp.async.commit_group;");
    };

    issue(0);
    if (T > 1) issue(1);

    const int a_mi = lane >> 3;
    const int a_row = (a_mi & 1) * 8 + (lane & 7);
    const int a_col = (a_mi >> 1) * 8;
    const int b_row = ((lane >> 3) & 1) * 8 + (lane & 7);
    const int b_col = (lane >> 4) * 8;

    for (int t = 0; t < T; t++) {
        if (t < T - 1) { asm volatile("cp.async.wait_group 1;"); }
        else           { asm volatile("cp.async.wait_group 0;"); }
        __syncthreads();

        int s = t % 3;
        uint32_t ab = sb + s * HA_ST;
        uint32_t bb = sb + 3 * HA_ST + s * HB_ST;

#pragma unroll
        for (int ks = 0; ks < 2; ks++) {
            const int kk = ks * 16;
            uint32_t a[4][4], br[2][4];
#pragma unroll
            for (int mt = 0; mt < 4; mt++) {
                int mb = warpM * 64 + mt * 16;
                uint32_t addr = ab + (mb + a_row) * 80 + (kk + a_col) * 2;
                LDSM_X4(a[mt][0], a[mt][1], a[mt][2], a[mt][3], addr);
            }
#pragma unroll
            for (int bt = 0; bt < 2; bt++) {
                int nb0 = warpN * 32 + bt * 16;
                uint32_t addr = bb + (kk + b_row) * 272 + (nb0 + b_col) * 2;
                LDSM_X4_T(br[bt][0], br[bt][1], br[bt][2], br[bt][3], addr);
            }
#pragma unroll
            for (int mt = 0; mt < 4; mt++)
#pragma unroll
                for (int nt = 0; nt < 4; nt++)
                    mma_f16(acc[mt][nt], a[mt][0], a[mt][1], a[mt][2], a[mt][3],
                            br[nt >> 1][(nt & 1) * 2], br[nt >> 1][(nt & 1) * 2 + 1]);
        }

        if (t + 2 < T) issue(t + 2);
    }

#pragma unroll
    for (int mt = 0; mt < 4; mt++) {
#pragma unroll
        for (int nt = 0; nt < 4; nt++) {
#pragma unroll
            for (int half = 0; half < 2; half++) {
                int m = row0 + warpM * 64 + mt * 16 + grp + half * 8;
                int n = col0 + warpN * 32 + nt * 8 + thr * 2;
                float v0 = acc[mt][nt][half * 2 + 0];
                float v1 = acc[mt][nt][half * 2 + 1];
                if (bias) { v0 += bias[n]; v1 += bias[n + 1]; }
                if (act) {
                    v0 = 0.5f * v0 * (1.0f + erff(v0 * 0.70710678118654752f));
                    v1 = 0.5f * v1 * (1.0f + erff(v1 * 0.70710678118654752f));
                }
                if (resid) {
                    v0 += resid[(size_t)m * N + n];
                    v1 += resid[(size_t)m * N + n + 1];
                }
                if (C) {
                    C[(size_t)m * N + n] = v0;
                    C[(size_t)m * N + n + 1] = v1;
                }
                if (Ch) {
                    __half2 hv = __floats2half2_rn(v0, v1);
                    *(uint32_t*)&Ch[(size_t)m * N + n] = *(uint32_t*)&hv;
                }
            }
        }
    }
}

__global__ __launch_bounds__(256, 2)
void gemm_h_kernel(const __half* A, const __half* B, const float* bias,
                   const float* resid, float* C, __half* Ch,
                   int M, int N, int K, int act) {
    extern __shared__ char smem[];
    gemm_h_body(A, B, bias, resid, C, Ch, M, N, K, act, smem);
}

__global__ __launch_bounds__(256, 2)
void gemm_h_qkv_kernel(const __half* A0, const __half* A1, const __half* A2,
                       const __half* B0, const __half* B1, const __half* B2,
                       const float* c0, const float* c1, const float* c2,
                       float* C0, float* C1, float* C2, int M, int N, int K) {
    extern __shared__ char smem[];
    const __half* A = blockIdx.z == 0 ? A0 : (blockIdx.z == 1 ? A1 : A2);
    const __half* B = blockIdx.z == 0 ? B0 : (blockIdx.z == 1 ? B1 : B2);
    const float* c = blockIdx.z == 0 ? c0 : (blockIdx.z == 1 ? c1 : c2);
    float* C = blockIdx.z == 0 ? C0 : (blockIdx.z == 1 ? C1 : C2);
    gemm_h_body(A, B, c, nullptr, C, nullptr, M, N, K, 0, smem);
}

// ---------------------------------------------------------------------------
// compute_M v3: idx generation inlined (bit-identical threefry draws)
// ---------------------------------------------------------------------------
__global__ __launch_bounds__(256)
void compute_M_kernel(const float* __restrict__ Q, const float* __restrict__ Kp,
                      uint32_t ka, uint32_t kb, float* __restrict__ Mout) {
    int warp = threadIdx.x >> 5, lane = threadIdx.x & 31;
    int bhl = blockIdx.x * 8 + warp;
    int l = bhl & (SEQ - 1);
    int bh = bhl >> 10;
    int h = bh & (NH - 1);
    int b = bh >> 4;

    // generate this row's 35 idx values: lane j -> sample j; lanes 0-2 -> 32..34
    int id0 = draw_idx(ka, kb, (uint32_t)(l * NSAMP + lane));
    int id1 = (lane < 3) ? draw_idx(ka, kb, (uint32_t)(l * NSAMP + 32 + lane)) : 0;

    const float* q = Q + ((size_t)(b * SEQ + l)) * DM + h * DK;
    float q0 = q[lane], q1 = q[lane + 32];
    const float* Kb = Kp + (size_t)b * SEQ * DM + h * DK;

    float mx = -1e38f, sm = 0.0f;
#pragma unroll 1
    for (int s = 0; s < NSAMP; s += 5) {
        float p[5];
#pragma unroll
        for (int j = 0; j < 5; j++) {
            int sj = s + j;
            int ki = (sj < 32) ? __shfl_sync(0xffffffffu, id0, sj)
                               : __shfl_sync(0xffffffffu, id1, sj - 32);
            const float* kr = Kb + (size_t)ki * DM;
            p[j] = q0 * kr[lane] + q1 * kr[lane + 32];
        }
#pragma unroll
        for (int o = 16; o; o >>= 1) {
#pragma unroll
            for (int j = 0; j < 5; j++)
                p[j] += __shfl_xor_sync(0xffffffffu, p[j], o);
        }
#pragma unroll
        for (int j = 0; j < 5; j++) { mx = fmaxf(mx, p[j]); sm += p[j]; }
    }
    if (lane == 0) Mout[bhl] = mx - sm * (1.0f / (float)SEQ);
}

// ---------------------------------------------------------------------------
// topk (frozen)
// ---------------------------------------------------------------------------
__global__ __launch_bounds__(1024)
void topk_kernel(const float* __restrict__ Min, int* __restrict__ top) {
    int bh = blockIdx.x;
    int tid = threadIdx.x;
    int lane = tid & 31, w = tid >> 5;
    __shared__ float wv[32];
    __shared__ int   wi[32];
    __shared__ int   winner;

    float val = Min[(size_t)bh * SEQ + tid];

    for (int u = 0; u < NTOP; u++) {
        float v = val;
        int i = tid;
#pragma unroll
        for (int o = 16; o; o >>= 1) {
            float vo = __shfl_xor_sync(0xffffffffu, v, o);
            int io = __shfl_xor_sync(0xffffffffu, i, o);
            if (vo > v || (vo == v && io < i)) { v = vo; i = io; }
        }
        if (lane == 0) { wv[w] = v; wi[w] = i; }
        __syncthreads();
        if (w == 0) {
            v = wv[lane]; i = wi[lane];
#pragma unroll
            for (int o = 16; o; o >>= 1) {
                float vo = __shfl_xor_sync(0xffffffffu, v, o);
                int io = __shfl_xor_sync(0xffffffffu, i, o);
                if (vo > v || (vo == v && io < i)) { v = vo; i = io; }
            }
            if (lane == 0) { top[bh * NTOP + u] = i; winner = i; }
        }
        __syncthreads();
        if (tid == winner) val = -1e38f;
    }
}

// ---------------------------------------------------------------------------
// vmean+fill fused: one block per (b,h) computes mean and broadcasts into hctx
// ---------------------------------------------------------------------------
__global__ void vmean_fill_kernel(const float* __restrict__ V, __half* __restrict__ hctx) {
    __shared__ float part[4][DK];
    __shared__ uint2 hv[16];
    int bh = blockIdx.x;
    int b = bh >> 4, h = bh & (NH - 1);
    int d = threadIdx.x & 63, qtr = threadIdx.x >> 6;
    const float* base = V + ((size_t)(b * SEQ + qtr * 256)) * DM + h * DK + d;
    float s = 0.0f;
#pragma unroll 8
    for (int i = 0; i < 256; i++) s += base[(size_t)i * DM];
    part[qtr][d] = s;
    __syncthreads();
    if (qtr == 0) {
        float m = (part[0][d] + part[1][d] + part[2][d] + part[3][d]) * (1.0f / (float)SEQ);
        part[0][d] = m;
    }
    __syncthreads();
    if (threadIdx.x < 16) {
        int c = threadIdx.x;
        __half2 h0 = __floats2half2_rn(part[0][c * 4 + 0], part[0][c * 4 + 1]);
        __half2 h1 = __floats2half2_rn(part[0][c * 4 + 2], part[0][c * 4 + 3]);
        uint2 o = { *(uint32_t*)&h0, *(uint32_t*)&h1 };
        hv[c] = o;
    }
    __syncthreads();
    // broadcast: 1024 rows x 16 uint2 each
    __half* hbase = hctx + ((size_t)b * SEQ) * DM + h * DK;
    for (int i = threadIdx.x; i < SEQ * 16; i += 256) {
        int row = i >> 4, c = i & 15;
        ((uint2*)(hbase + (size_t)row * DM))[c] = hv[c];
    }
}

// ---------------------------------------------------------------------------
// attn (2-way u-split; R12 measured-best config)
// ---------------------------------------------------------------------------
constexpr int USPL = 18;
constexpr int KSTR2 = 68;
constexpr int OFF_RDEN = USPL * DK;
constexpr int OFF_KS   = 1192;
constexpr int OFF_SC   = OFF_KS + 64 * KSTR2;
constexpr int ATTN_SMEM = (OFF_SC + USPL * SEQ) * 4;

__global__ __launch_bounds__(256)
void attn_bh_kernel(const float* __restrict__ Q, const float* __restrict__ Kp,
                    const float* __restrict__ V, const int* __restrict__ top,
                    __half* __restrict__ hctx) {
    extern __shared__ float dsm[];
    float* qs   = dsm;
    float* rden = dsm + OFF_RDEN;
    float* ks   = dsm + OFF_KS;
    float* sc   = dsm + OFF_SC;

    int bh = blockIdx.x;
    int b = bh >> 4, h = bh & (NH - 1);
    const int z = blockIdx.y;
    const int u0 = z * USPL;
    const int nu = z == 0 ? USPL : (NTOP - USPL);
    int tid = threadIdx.x;
    int lane = tid & 31, warp = tid >> 5;

    for (int i = tid; i < nu * DK; i += 256) {
        int u = i >> 6, d = i & 63;
        int qr = top[bh * NTOP + u0 + u];
        qs[u * DK + d] = tf32r(Q[((size_t)(b * SEQ + qr)) * DM + h * DK + d]);
    }
    __syncthreads();

    const int key = tid & 63, ug = tid >> 6;

    for (int kt = 0; kt < 16; kt++) {
        for (int i = tid; i < 1024; i += 256) {
            int kr = i >> 4, d4 = i & 15;
            float4 vv = *(const float4*)&Kp[((size_t)(b * SEQ + kt * 64 + kr)) * DM + h * DK + d4 * 4];
            float* dst = &ks[kr * KSTR2 + d4 * 4];
            dst[0] = tf32r(vv.x); dst[1] = tf32r(vv.y);
            dst[2] = tf32r(vv.z); dst[3] = tf32r(vv.w);
        }
        __syncthreads();

        float4 kv[16];
        const float4* krow = (const float4*)&ks[key * KSTR2];
#pragma unroll
        for (int c = 0; c < 16; c++) kv[c] = krow[c];

        for (int u = ug; u < nu; u += 4) {
            const float4* qrow = (const float4*)&qs[u * DK];
            float a = 0.0f;
#pragma unroll
            for (int c = 0; c < 16; c++) {
                float4 qv = qrow[c];
                a += qv.x * kv[c].x + qv.y * kv[c].y + qv.z * kv[c].z + qv.w * kv[c].w;
            }
            sc[u * SEQ + kt * 64 + key] = a * 0.125f;
        }
        __syncthreads();
    }

    for (int u = warp; u < nu; u += 8) {
        float m = -1e38f;
        for (int i = lane; i < SEQ; i += 32) m = fmaxf(m, sc[u * SEQ + i]);
#pragma unroll
        for (int o = 16; o; o >>= 1) m = fmaxf(m, __shfl_xor_sync(0xffffffffu, m, o));
        float s = 0.0f;
        for (int i = lane; i < SEQ; i += 32) {
            float e = expf(sc[u * SEQ + i] - m);
            sc[u * SEQ + i] = e;
            s += e;
        }
#pragma unroll
        for (int o = 16; o; o >>= 1) s += __shfl_xor_sync(0xffffffffu, s, o);
        if (lane == 0) rden[u] = 1.0f / s;
    }
    __syncthreads();

    for (int f = tid; f < nu * SEQ; f += 256) {
        int u = f >> 10;
        sc[f] = tf32r(sc[f] * rden[u]);
    }
    __syncthreads();

    const int d = key;
    float acc[5];
#pragma unroll
    for (int j = 0; j < 5; j++) acc[j] = 0.0f;

    for (int kt = 0; kt < 16; kt++) {
        for (int i = tid; i < 1024; i += 256) {
            int kr = i >> 4, d4 = i & 15;
            float4 vv = *(const float4*)&V[((size_t)(b * SEQ + kt * 64 + kr)) * DM + h * DK + d4 * 4];
            float* dst = &ks[kr * KSTR2 + d4 * 4];
            dst[0] = tf32r(vv.x); dst[1] = tf32r(vv.y);
            dst[2] = tf32r(vv.z); dst[3] = tf32r(vv.w);
        }
        __syncthreads();

#pragma unroll 4
        for (int kb = 0; kb < 64; kb += 4) {
            float v0 = ks[(kb + 0) * KSTR2 + d];
            float v1 = ks[(kb + 1) * KSTR2 + d];
            float v2 = ks[(kb + 2) * KSTR2 + d];
            float v3 = ks[(kb + 3) * KSTR2 + d];
            int j = 0;
            for (int u = ug; u < nu; u += 4, j++) {
                float4 s4 = *(const float4*)&sc[u * SEQ + kt * 64 + kb];
                acc[j] += s4.x * v0 + s4.y * v1 + s4.z * v2 + s4.w * v3;
            }
        }
        __syncthreads();
    }

    int j = 0;
    for (int u = ug; u < nu; u += 4, j++) {
        int qr = top[bh * NTOP + u0 + u];
        hctx[((size_t)(b * SEQ + qr)) * DM + h * DK + d] = __float2half_rn(acc[j]);
    }
}

// ---------------------------------------------------------------------------
// BatchNorm v3 (frozen)
// ---------------------------------------------------------------------------
__global__ void bn_partial_kernel(const float* __restrict__ x) {
    int blk = blockIdx.x;
    int tid = threadIdx.x;
    float s[4] = {0, 0, 0, 0}, q[4] = {0, 0, 0, 0};
    const float* base = x + (size_t)blk * 64 * DM;
    for (int r = 0; r < 64; r++) {
#pragma unroll
        for (int j = 0; j < 4; j++) {
            float v = base[(size_t)r * DM + tid + j * 256];
            s[j] += v; q[j] += v * v;
        }
    }
#pragma unroll
    for (int j = 0; j < 4; j++) {
        g_psum[blk * DM + tid + j * 256] = s[j];
        g_psq[blk * DM + tid + j * 256] = q[j];
    }
}

__global__ void bn_final_kernel(float* __restrict__ mu, float* __restrict__ rstd) {
    int c = blockIdx.x * 256 + threadIdx.x;
    float s = 0.0f, q = 0.0f;
#pragma unroll 8
    for (int r = 0; r < 64; r++) {
        s += g_psum[r * DM + c];
        q += g_psq[r * DM + c];
    }
    float m = s * (1.0f / (float)ROWS);
    float v = q * (1.0f / (float)ROWS) - m * m;
    mu[c] = m;
    rstd[c] = rsqrtf(v + 1e-5f);
}

__global__ void bn_apply4_kernel(const float* __restrict__ x, const float* __restrict__ mu,
                                 const float* __restrict__ rstd, const float* __restrict__ g,
                                 const float* __restrict__ bta, float* __restrict__ y,
                                 __half* __restrict__ yh) {
    size_t i = (size_t)blockIdx.x * 256 + threadIdx.x;
    int c4 = (int)(i & 255);
    float4 xv = ((const float4*)x)[i];
    float4 m = ((const float4*)mu)[c4];
    float4 r = ((const float4*)rstd)[c4];
    float4 gg = ((const float4*)g)[c4];
    float4 bb = ((const float4*)bta)[c4];
    float4 o;
    o.x = (xv.x - m.x) * r.x * gg.x + bb.x;
    o.y = (xv.y - m.y) * r.y * gg.y + bb.y;
    o.z = (xv.z - m.z) * r.z * gg.z + bb.z;
    o.w = (xv.w - m.w) * r.w * gg.w + bb.w;
    ((float4*)y)[i] = o;
    if (yh) {
        __half2 h0 = __floats2half2_rn(o.x, o.y);
        __half2 h1 = __floats2half2_rn(o.z, o.w);
        uint2 ho = { *(uint32_t*)&h0, *(uint32_t*)&h1 };
        ((uint2*)yh)[i] = ho;
    }
}

// ---------------------------------------------------------------------------
// Launch helpers
// ---------------------------------------------------------------------------
static void run_gemm(const __half* A, const __half* B, const float* bias,
                     const float* resid, float* C, __half* Ch,
                     int M, int N, int K, int act) {
    dim3 grid(N / 128, M / 128);
    gemm_h_kernel<<<grid, 256, H_SMEM>>>(A, B, bias, resid, C, Ch, M, N, K, act);
}

static void run_bn(const float* x, float* mu, float* rs,
                   const float* g, const float* bta, float* y, __half* yh) {
    bn_partial_kernel<<<64, 256>>>(x);
    bn_final_kernel<<<4, 256>>>(mu, rs);
    bn_apply4_kernel<<<(int)(NELEM / 4 / 256), 256>>>(x, mu, rs, g, bta, y, yh);
}

extern "C" void kernel_launch(void* const* d_in, const int* in_sizes, int n_in,
                              void* d_out, int out_size) {
    const float* tgt   = (const float*)d_in[0];
    const float* mem   = (const float*)d_in[1];
    const float* sa_wq = (const float*)d_in[2];
    const float* sa_bq = (const float*)d_in[3];
    const float* sa_wk = (const float*)d_in[4];
    const float* sa_bk = (const float*)d_in[5];
    const float* sa_wv = (const float*)d_in[6];
    const float* sa_bv = (const float*)d_in[7];
    const float* sa_wo = (const float*)d_in[8];
    const float* sa_bo = (const float*)d_in[9];
    const float* ca_wq = (const float*)d_in[10];
    const float* ca_bq = (const float*)d_in[11];
    const float* ca_wk = (const float*)d_in[12];
    const float* ca_bk = (const float*)d_in[13];
    const float* ca_wv = (const float*)d_in[14];
    const float* ca_bv = (const float*)d_in[15];
    const float* ca_wo = (const float*)d_in[16];
    const float* ca_bo = (const float*)d_in[17];
    const float* w1    = (const float*)d_in[18];
    const float* b1    = (const float*)d_in[19];
    const float* w2    = (const float*)d_in[20];
    const float* b2    = (const float*)d_in[21];
    const float* bn1_g = (const float*)d_in[22];
    const float* bn1_b = (const float*)d_in[23];
    const float* bn2_g = (const float*)d_in[24];
    const float* bn2_b = (const float*)d_in[25];
    const float* bn3_g = (const float*)d_in[26];
    const float* bn3_b = (const float*)d_in[27];
    float* out = (float*)d_out;

    cudaFuncSetAttribute(gemm_h_kernel, cudaFuncAttributeMaxDynamicSharedMemorySize, H_SMEM);
    cudaFuncSetAttribute(gemm_h_qkv_kernel, cudaFuncAttributeMaxDynamicSharedMemorySize, H_SMEM);
    cudaFuncSetAttribute(attn_bh_kernel, cudaFuncAttributeMaxDynamicSharedMemorySize, ATTN_SMEM);

    float *q, *k, *v, *xin, *x1, *x2, *Mb, *mu, *rs;
    int *top;
    __half *htgt, *hmem, *hx1, *hx2, *hctx, *hh, *hwq, *hwk, *hwv, *hwo, *hw1, *hw2;
    cudaGetSymbolAddress((void**)&q,    g_q);
    cudaGetSymbolAddress((void**)&k,    g_k);
    cudaGetSymbolAddress((void**)&v,    g_v);
    cudaGetSymbolAddress((void**)&xin,  g_xin);
    cudaGetSymbolAddress((void**)&x1,   g_x1);
    cudaGetSymbolAddress((void**)&x2,   g_x2);
    cudaGetSymbolAddress((void**)&Mb,   g_M);
    cudaGetSymbolAddress((void**)&top,  g_top);
    cudaGetSymbolAddress((void**)&mu,   g_mu);
    cudaGetSymbolAddress((void**)&rs,   g_rstd);
    cudaGetSymbolAddress((void**)&htgt, g_htgt);
    cudaGetSymbolAddress((void**)&hmem, g_hmem);
    cudaGetSymbolAddress((void**)&hx1,  g_hx1);
    cudaGetSymbolAddress((void**)&hx2,  g_hx2);
    cudaGetSymbolAddress((void**)&hctx, g_hctx);
    cudaGetSymbolAddress((void**)&hh,   g_hh);
    cudaGetSymbolAddress((void**)&hwq,  g_hwq);
    cudaGetSymbolAddress((void**)&hwk,  g_hwk);
    cudaGetSymbolAddress((void**)&hwv,  g_hwv);
    cudaGetSymbolAddress((void**)&hwo,  g_hwo);
    cudaGetSymbolAddress((void**)&hw1,  g_hw1);
    cudaGetSymbolAddress((void**)&hw2,  g_hw2);

    // Key derivation (frozen): root=key(42); k1,k2=split(root); randint uses split(rng)[1]
    uint32_t r1a, r1b, r2a, r2b;
    uint32_t s1a, s1b, s2a, s2b;
#if RNG_PARTITIONABLE
    tf2x32(0u, 42u, 0u, 0u, r1a, r1b);
    tf2x32(0u, 42u, 0u, 1u, r2a, r2b);
    tf2x32(r1a, r1b, 0u, 1u, s1a, s1b);
    tf2x32(r2a, r2b, 0u, 1u, s2a, s2b);
#else
    {
        uint32_t a0, b0, a1, b1;
        tf2x32(0u, 42u, 0u, 2u, a0, b0);
        tf2x32(0u, 42u, 1u, 3u, a1, b1);
        r1a = a0; r1b = a1;
        r2a = b0; r2b = b1;
        tf2x32(r1a, r1b, 0u, 2u, a0, b0);
        tf2x32(r1a, r1b, 1u, 3u, a1, b1);
        s1a = b0; s1b = b1;
        tf2x32(r2a, r2b, 0u, 2u, a0, b0);
        tf2x32(r2a, r2b, 1u, 3u, a1, b1);
        s2a = b0; s2b = b1;
    }
#endif

    const int M_BLKS = BATCH * NH * SEQ / 8;
    dim3 qkv_grid(DM / 128, ROWS / 128, 3);
    dim3 attn_grid(BATCH * NH, 2);

    // ================= Self-attention =================
    run_f2h(tgt, htgt, NELEM);
    run_f2h(sa_wq, hwq, (size_t)DM * DM);
    run_f2h(sa_wk, hwk, (size_t)DM * DM);
    run_f2h(sa_wv, hwv, (size_t)DM * DM);
    gemm_h_qkv_kernel<<<qkv_grid, 256, H_SMEM>>>(
        htgt, htgt, htgt, hwq, hwk, hwv, sa_bq, sa_bk, sa_bv,
        q, k, v, ROWS, DM, DM);
    run_f2h(mem, hmem, NELEM);
    run_f2h(sa_wo, hwo, (size_t)DM * DM);
    compute_M_kernel<<<M_BLKS, 256>>>(q, k, s1a, s1b, Mb);
    topk_kernel<<<BATCH * NH, 1024>>>(Mb, top);
    vmean_fill_kernel<<<BATCH * NH, 256>>>(v, hctx);
    attn_bh_kernel<<<attn_grid, 256, ATTN_SMEM>>>(q, k, v, top, hctx);
    run_gemm(hctx, hwo, sa_bo, tgt, xin, nullptr, ROWS, DM, DM, 0);
    run_bn(xin, mu, rs, bn1_g, bn1_b, x1, hx1);

    // ================= Cross-attention =================
    run_f2h(ca_wq, hwq, (size_t)DM * DM);
    run_f2h(ca_wk, hwk, (size_t)DM * DM);
    run_f2h(ca_wv, hwv, (size_t)DM * DM);
    run_f2h(ca_wo, hwo, (size_t)DM * DM);
    gemm_h_qkv_kernel<<<qkv_grid, 256, H_SMEM>>>(
        hx1, hmem, hmem, hwq, hwk, hwv, ca_bq, ca_bk, ca_bv,
        q, k, v, ROWS, DM, DM);
    compute_M_kernel<<<M_BLKS, 256>>>(q, k, s2a, s2b, Mb);
    topk_kernel<<<BATCH * NH, 1024>>>(Mb, top);
    vmean_fill_kernel<<<BATCH * NH, 256>>>(v, hctx);
    attn_bh_kernel<<<attn_grid, 256, ATTN_SMEM>>>(q, k, v, top, hctx);
    run_gemm(hctx, hwo, ca_bo, x1, xin, nullptr, ROWS, DM, DM, 0);
    run_bn(xin, mu, rs, bn2_g, bn2_b, x2, hx2);

    // ================= FFN =================
    run_f2h(w1, hw1, (size_t)DM * DFF);
    run_f2h(w2, hw2, (size_t)DM * DFF);
    run_gemm(hx2, hw1, b1, nullptr, nullptr, hh, ROWS, DFF, DM, 1);
    run_gemm(hh, hw2, b2, x2, xin, nullptr, ROWS, DM, DFF, 0);
    run_bn(xin, mu, rs, bn3_g, bn3_b, out, nullptr);
}

// round 17
// speedup vs baseline: 1.0171x; 1.0171x over previous
#include <cuda_runtime.h>
#include <cuda_fp16.h>
#include <cstdint>
#include <math.h>

#define RNG_PARTITIONABLE 1   // confirmed passing config -- do not change

constexpr int BATCH = 4, SEQ = 1024, DM = 1024, NH = 16, DK = 64, DFF = 4096;
constexpr int NSAMP = 35;
constexpr int NTOP  = 35;
constexpr int ROWS  = BATCH * SEQ;
constexpr size_t NELEM = (size_t)ROWS * DM;
constexpr int IDX_N = SEQ * NSAMP;
constexpr int IDX_HALF = IDX_N / 2;

// ---------------------------------------------------------------------------
// Static device scratch
// ---------------------------------------------------------------------------
__device__ float g_q[NELEM];
__device__ float g_k[NELEM];
__device__ float g_v[NELEM];
__device__ float g_xin[NELEM];
__device__ float g_x1[NELEM];
__device__ float g_x2[NELEM];
__device__ float g_M[BATCH * NH * SEQ];
__device__ float g_vmean[BATCH * NH * DK];
__device__ int   g_top[BATCH * NH * NTOP];
__device__ int   g_idx[IDX_N];
__device__ float g_mu[DM];
__device__ float g_rstd[DM];
__device__ float g_bsum[DM];
__device__ float g_bsq[DM];
// fp16 buffers
__device__ __half g_htgt[NELEM];
__device__ __half g_hmem[NELEM];
__device__ __half g_hx1[NELEM];
__device__ __half g_hx2[NELEM];
__device__ __half g_hctx[NELEM];
__device__ __half g_hh[(size_t)ROWS * DFF];
__device__ __half g_hwq[DM * DM];
__device__ __half g_hwk[DM * DM];
__device__ __half g_hwv[DM * DM];
__device__ __half g_hwo[DM * DM];
__device__ __half g_hw1[(size_t)DM * DFF];
__device__ __half g_hw2[(size_t)DM * DFF];

// ---------------------------------------------------------------------------
// Helpers
// ---------------------------------------------------------------------------
__device__ __forceinline__ float tf32r(float x) {
    uint32_t u;
    asm("cvt.rna.tf32.f32 %0, %1;" : "=r"(u) : "f"(x));
    return __uint_as_float(u);
}

__device__ __forceinline__ uint32_t saddr(const void* p) {
    return (uint32_t)__cvta_generic_to_shared(p);
}

__device__ __forceinline__ void cp16(uint32_t dst, const void* src) {
    asm volatile("cp.async.cg.shared.global [%0], [%1], 16;" :: "r"(dst), "l"(src));
}

#define LDSM_X4(r0, r1, r2, r3, a) \
    asm volatile("ldmatrix.sync.aligned.m8n8.x4.shared.b16 {%0,%1,%2,%3}, [%4];" \
                 : "=r"(r0), "=r"(r1), "=r"(r2), "=r"(r3) : "r"(a))

#define LDSM_X4_T(r0, r1, r2, r3, a) \
    asm volatile("ldmatrix.sync.aligned.m8n8.x4.trans.shared.b16 {%0,%1,%2,%3}, [%4];" \
                 : "=r"(r0), "=r"(r1), "=r"(r2), "=r"(r3) : "r"(a))

__device__ __forceinline__ void mma_f16(float c[4], uint32_t a0, uint32_t a1,
                                        uint32_t a2, uint32_t a3,
                                        uint32_t b0, uint32_t b1) {
    asm volatile(
        "mma.sync.aligned.m16n8k16.row.col.f32.f16.f16.f32 "
        "{%0,%1,%2,%3}, {%4,%5,%6,%7}, {%8,%9}, {%0,%1,%2,%3};"
        : "+f"(c[0]), "+f"(c[1]), "+f"(c[2]), "+f"(c[3])
        : "r"(a0), "r"(a1), "r"(a2), "r"(a3), "r"(b0), "r"(b1));
}

// ---------------------------------------------------------------------------
// threefry2x32 (frozen)
// ---------------------------------------------------------------------------
__host__ __device__ __forceinline__ void tf2x32(uint32_t k0, uint32_t k1,
                                                uint32_t x0, uint32_t x1,
                                                uint32_t &o0, uint32_t &o1) {
    uint32_t ks2 = k0 ^ k1 ^ 0x1BD11BDAu;
    x0 += k0; x1 += k1;
#define TF_R(r) { x0 += x1; x1 = (x1 << (r)) | (x1 >> (32 - (r))); x1 ^= x0; }
    TF_R(13) TF_R(15) TF_R(26) TF_R(6)
    x0 += k1; x1 += ks2 + 1u;
    TF_R(17) TF_R(29) TF_R(16) TF_R(24)
    x0 += ks2; x1 += k0 + 2u;
    TF_R(13) TF_R(15) TF_R(26) TF_R(6)
    x0 += k0; x1 += k1 + 3u;
    TF_R(17) TF_R(29) TF_R(16) TF_R(24)
    x0 += k1; x1 += ks2 + 4u;
    TF_R(13) TF_R(15) TF_R(26) TF_R(6)
    x0 += ks2; x1 += k0 + 5u;
#undef TF_R
    o0 = x0; o1 = x1;
}

__global__ void make_idx_kernel(uint32_t ka, uint32_t kb, int* __restrict__ out) {
    int j = blockIdx.x * blockDim.x + threadIdx.x;
    if (j >= IDX_N) return;
    uint32_t o0, o1;
#if RNG_PARTITIONABLE
    tf2x32(ka, kb, 0u, (uint32_t)j, o0, o1);
    out[j] = (int)((o0 ^ o1) & 1023u);
#else
    if (j < IDX_HALF) {
        tf2x32(ka, kb, (uint32_t)j, (uint32_t)(IDX_HALF + j), o0, o1);
        out[j] = (int)(o0 & 1023u);
    } else {
        tf2x32(ka, kb, (uint32_t)(j - IDX_HALF), (uint32_t)j, o0, o1);
        out[j] = (int)(o1 & 1023u);
    }
#endif
}

// ---------------------------------------------------------------------------
// f32 -> f16 conversion (RN), vectorized
// ---------------------------------------------------------------------------
__global__ void f2h_kernel(const float* __restrict__ x, __half* __restrict__ y) {
    size_t i = (size_t)blockIdx.x * 256 + threadIdx.x;
    float4 v = ((const float4*)x)[i];
    __half2 h0 = __floats2half2_rn(v.x, v.y);
    __half2 h1 = __floats2half2_rn(v.z, v.w);
    uint2 o = { *(uint32_t*)&h0, *(uint32_t*)&h1 };
    ((uint2*)y)[i] = o;
}

static void run_f2h(const float* x, __half* y, size_t n) {
    f2h_kernel<<<(int)(n / 4 / 256), 256>>>(x, y);
}

// ---------------------------------------------------------------------------
// FP16 tensor-core GEMM: 128x128x32 tiles, 3-stage cp.async (measured best)
// ---------------------------------------------------------------------------
constexpr int HA_ST = 10240;
constexpr int HB_ST = 8704;
constexpr int H_SMEM = 3 * (HA_ST + HB_ST);

__device__ __forceinline__ void gemm_h_body(const __half* __restrict__ A,
                                            const __half* __restrict__ B,
                                            const float* __restrict__ bias,
                                            const float* __restrict__ resid,
                                            float* __restrict__ C,
                                            __half* __restrict__ Ch,
                                            int M, int N, int K, int act, char* smem) {
    uint32_t sb = saddr(smem);
    const int tid = threadIdx.x;
    const int lane = tid & 31, warp = tid >> 5;
    const int warpM = warp >> 2, warpN = warp & 3;
    const int grp = lane >> 2, thr = lane & 3;
    const int row0 = blockIdx.y * 128, col0 = blockIdx.x * 128;
    const int T = K / 32;

    float acc[4][4][4];
#pragma unroll
    for (int mt = 0; mt < 4; mt++)
#pragma unroll
        for (int nt = 0; nt < 4; nt++)
#pragma unroll
            for (int i = 0; i < 4; i++) acc[mt][nt][i] = 0.0f;

    auto issue = [&](int t) {
        int s = t % 3;
        uint32_t ab = sb + s * HA_ST;
        uint32_t bb = sb + 3 * HA_ST + s * HB_ST;
#pragma unroll
        for (int i = 0; i < 2; i++) {
            int f = tid + i * 256;
            int ar = f >> 2, ac = f & 3;
            cp16(ab + ar * 80 + ac * 16, &A[(size_t)(row0 + ar) * K + t * 32 + ac * 8]);
            int br = f >> 4, bc = f & 15;
            cp16(bb + br * 272 + bc * 16, &B[(size_t)(t * 32 + br) * N + col0 + bc * 8]);
        }
        asm volatile("cp.async.commit_group;");
    };

    issue(0);
    if (T > 1) issue(1);

    const int a_mi = lane >> 3;
    const int a_row = (a_mi & 1) * 8 + (lane & 7);
    const int a_col = (a_mi >> 1) * 8;
    const int b_row = ((lane >> 3) & 1) * 8 + (lane & 7);
    const int b_col = (lane >> 4) * 8;

    for (int t = 0; t < T; t++) {
        if (t < T - 1) { asm volatile("cp.async.wait_group 1;"); }
        else           { asm volatile("cp.async.wait_group 0;"); }
        __syncthreads();

        int s = t % 3;
        uint32_t ab = sb + s * HA_ST;
        uint32_t bb = sb + 3 * HA_ST + s * HB_ST;

#pragma unroll
        for (int ks = 0; ks < 2; ks++) {
            const int kk = ks * 16;
            uint32_t a[4][4], br[2][4];
#pragma unroll
            for (int mt = 0; mt < 4; mt++) {
                int mb = warpM * 64 + mt * 16;
                uint32_t addr = ab + (mb + a_row) * 80 + (kk + a_col) * 2;
                LDSM_X4(a[mt][0], a[mt][1], a[mt][2], a[mt][3], addr);
            }
#pragma unroll
            for (int bt = 0; bt < 2; bt++) {
                int nb0 = warpN * 32 + bt * 16;
                uint32_t addr = bb + (kk + b_row) * 272 + (nb0 + b_col) * 2;
                LDSM_X4_T(br[bt][0], br[bt][1], br[bt][2], br[bt][3], addr);
            }
#pragma unroll
            for (int mt = 0; mt < 4; mt++)
#pragma unroll
                for (int nt = 0; nt < 4; nt++)
                    mma_f16(acc[mt][nt], a[mt][0], a[mt][1], a[mt][2], a[mt][3],
                            br[nt >> 1][(nt & 1) * 2], br[nt >> 1][(nt & 1) * 2 + 1]);
        }

        if (t + 2 < T) issue(t + 2);
    }

#pragma unroll
    for (int mt = 0; mt < 4; mt++) {
#pragma unroll
        for (int nt = 0; nt < 4; nt++) {
#pragma unroll
            for (int half = 0; half < 2; half++) {
                int m = row0 + warpM * 64 + mt * 16 + grp + half * 8;
                int n = col0 + warpN * 32 + nt * 8 + thr * 2;
                float v0 = acc[mt][nt][half * 2 + 0];
                float v1 = acc[mt][nt][half * 2 + 1];
                if (bias) { v0 += bias[n]; v1 += bias[n + 1]; }
                if (act) {
                    v0 = 0.5f * v0 * (1.0f + erff(v0 * 0.70710678118654752f));
                    v1 = 0.5f * v1 * (1.0f + erff(v1 * 0.70710678118654752f));
                }
                if (resid) {
                    v0 += resid[(size_t)m * N + n];
                    v1 += resid[(size_t)m * N + n + 1];
                }
                if (C) {
                    C[(size_t)m * N + n] = v0;
                    C[(size_t)m * N + n + 1] = v1;
                }
                if (Ch) {
                    __half2 hv = __floats2half2_rn(v0, v1);
                    *(uint32_t*)&Ch[(size_t)m * N + n] = *(uint32_t*)&hv;
                }
            }
        }
    }
}

__global__ __launch_bounds__(256, 2)
void gemm_h_kernel(const __half* A, const __half* B, const float* bias,
                   const float* resid, float* C, __half* Ch,
                   int M, int N, int K, int act) {
    extern __shared__ char smem[];
    gemm_h_body(A, B, bias, resid, C, Ch, M, N, K, act, smem);
}

__global__ __launch_bounds__(256, 2)
void gemm_h_qkv_kernel(const __half* A0, const __half* A1, const __half* A2,
                       const __half* B0, const __half* B1, const __half* B2,
                       const float* c0, const float* c1, const float* c2,
                       float* C0, float* C1, float* C2, int M, int N, int K) {
    extern __shared__ char smem[];
    const __half* A = blockIdx.z == 0 ? A0 : (blockIdx.z == 1 ? A1 : A2);
    const __half* B = blockIdx.z == 0 ? B0 : (blockIdx.z == 1 ? B1 : B2);
    const float* c = blockIdx.z == 0 ? c0 : (blockIdx.z == 1 ? c1 : c2);
    float* C = blockIdx.z == 0 ? C0 : (blockIdx.z == 1 ? C1 : C2);
    gemm_h_body(A, B, c, nullptr, C, nullptr, M, N, K, 0, smem);
}

// ---------------------------------------------------------------------------
// compute_M v2 (separate idx; measured best)
// ---------------------------------------------------------------------------
__global__ __launch_bounds__(256)
void compute_M_kernel(const float* __restrict__ Q, const float* __restrict__ Kp,
                      const int* __restrict__ idx, float* __restrict__ Mout) {
    int warp = threadIdx.x >> 5, lane = threadIdx.x & 31;
    int bhl = blockIdx.x * 8 + warp;
    int l = bhl & (SEQ - 1);
    int bh = bhl >> 10;
    int h = bh & (NH - 1);
    int b = bh >> 4;

    const float* q = Q + ((size_t)(b * SEQ + l)) * DM + h * DK;
    float q0 = q[lane], q1 = q[lane + 32];
    const int* row = idx + l * NSAMP;
    const float* Kb = Kp + (size_t)b * SEQ * DM + h * DK;

    float mx = -1e38f, sm = 0.0f;
#pragma unroll 1
    for (int s = 0; s < NSAMP; s += 5) {
        float p[5];
#pragma unroll
        for (int j = 0; j < 5; j++) {
            int ki = row[s + j];
            const float* kr = Kb + (size_t)ki * DM;
            p[j] = q0 * kr[lane] + q1 * kr[lane + 32];
        }
#pragma unroll
        for (int o = 16; o; o >>= 1) {
#pragma unroll
            for (int j = 0; j < 5; j++)
                p[j] += __shfl_xor_sync(0xffffffffu, p[j], o);
        }
#pragma unroll
        for (int j = 0; j < 5; j++) { mx = fmaxf(mx, p[j]); sm += p[j]; }
    }
    if (lane == 0) Mout[bhl] = mx - sm * (1.0f / (float)SEQ);
}

// ---------------------------------------------------------------------------
// topk (frozen)
// ---------------------------------------------------------------------------
__global__ __launch_bounds__(1024)
void topk_kernel(const float* __restrict__ Min, int* __restrict__ top) {
    int bh = blockIdx.x;
    int tid = threadIdx.x;
    int lane = tid & 31, w = tid >> 5;
    __shared__ float wv[32];
    __shared__ int   wi[32];
    __shared__ int   winner;

    float val = Min[(size_t)bh * SEQ + tid];

    for (int u = 0; u < NTOP; u++) {
        float v = val;
        int i = tid;
#pragma unroll
        for (int o = 16; o; o >>= 1) {
            float vo = __shfl_xor_sync(0xffffffffu, v, o);
            int io = __shfl_xor_sync(0xffffffffu, i, o);
            if (vo > v || (vo == v && io < i)) { v = vo; i = io; }
        }
        if (lane == 0) { wv[w] = v; wi[w] = i; }
        __syncthreads();
        if (w == 0) {
            v = wv[lane]; i = wi[lane];
#pragma unroll
            for (int o = 16; o; o >>= 1) {
                float vo = __shfl_xor_sync(0xffffffffu, v, o);
                int io = __shfl_xor_sync(0xffffffffu, i, o);
                if (vo > v || (vo == v && io < i)) { v = vo; i = io; }
            }
            if (lane == 0) { top[bh * NTOP + u] = i; winner = i; }
        }
        __syncthreads();
        if (tid == winner) val = -1e38f;
    }
}

// ---------------------------------------------------------------------------
// vmean v2 + fill (measured best)
// ---------------------------------------------------------------------------
__global__ void vmean_kernel(const float* __restrict__ V, float* __restrict__ vmean) {
    __shared__ float part[4][DK];
    int bh = blockIdx.x;
    int b = bh >> 4, h = bh & (NH - 1);
    int d = threadIdx.x & 63, qtr = threadIdx.x >> 6;
    const float* base = V + ((size_t)(b * SEQ + qtr * 256)) * DM + h * DK + d;
    float s = 0.0f;
#pragma unroll 8
    for (int i = 0; i < 256; i++) s += base[(size_t)i * DM];
    part[qtr][d] = s;
    __syncthreads();
    if (qtr == 0)
        vmean[bh * DK + d] = (part[0][d] + part[1][d] + part[2][d] + part[3][d]) * (1.0f / (float)SEQ);
}

__global__ void fill_ctx4_kernel(const float* __restrict__ vmean, __half* __restrict__ hctx) {
    size_t i = (size_t)blockIdx.x * 256 + threadIdx.x;
    int c4 = (int)(i & 255);
    int b = (int)(i >> 18);
    int h = c4 >> 4;
    float4 v = ((const float4*)vmean)[(b * NH + h) * 16 + (c4 & 15)];
    __half2 h0 = __floats2half2_rn(v.x, v.y);
    __half2 h1 = __floats2half2_rn(v.z, v.w);
    uint2 o = { *(uint32_t*)&h0, *(uint32_t*)&h1 };
    ((uint2*)hctx)[i] = o;
}

// ---------------------------------------------------------------------------
// attn (2-way u-split; measured best)
// ---------------------------------------------------------------------------
constexpr int USPL = 18;
constexpr int KSTR2 = 68;
constexpr int OFF_RDEN = USPL * DK;
constexpr int OFF_KS   = 1192;
constexpr int OFF_SC   = OFF_KS + 64 * KSTR2;
constexpr int ATTN_SMEM = (OFF_SC + USPL * SEQ) * 4;

__global__ __launch_bounds__(256)
void attn_bh_kernel(const float* __restrict__ Q, const float* __restrict__ Kp,
                    const float* __restrict__ V, const int* __restrict__ top,
                    __half* __restrict__ hctx) {
    extern __shared__ float dsm[];
    float* qs   = dsm;
    float* rden = dsm + OFF_RDEN;
    float* ks   = dsm + OFF_KS;
    float* sc   = dsm + OFF_SC;

    int bh = blockIdx.x;
    int b = bh >> 4, h = bh & (NH - 1);
    const int z = blockIdx.y;
    const int u0 = z * USPL;
    const int nu = z == 0 ? USPL : (NTOP - USPL);
    int tid = threadIdx.x;
    int lane = tid & 31, warp = tid >> 5;

    for (int i = tid; i < nu * DK; i += 256) {
        int u = i >> 6, d = i & 63;
        int qr = top[bh * NTOP + u0 + u];
        qs[u * DK + d] = tf32r(Q[((size_t)(b * SEQ + qr)) * DM + h * DK + d]);
    }
    __syncthreads();

    const int key = tid & 63, ug = tid >> 6;

    for (int kt = 0; kt < 16; kt++) {
        for (int i = tid; i < 1024; i += 256) {
            int kr = i >> 4, d4 = i & 15;
            float4 vv = *(const float4*)&Kp[((size_t)(b * SEQ + kt * 64 + kr)) * DM + h * DK + d4 * 4];
            float* dst = &ks[kr * KSTR2 + d4 * 4];
            dst[0] = tf32r(vv.x); dst[1] = tf32r(vv.y);
            dst[2] = tf32r(vv.z); dst[3] = tf32r(vv.w);
        }
        __syncthreads();

        float4 kv[16];
        const float4* krow = (const float4*)&ks[key * KSTR2];
#pragma unroll
        for (int c = 0; c < 16; c++) kv[c] = krow[c];

        for (int u = ug; u < nu; u += 4) {
            const float4* qrow = (const float4*)&qs[u * DK];
            float a = 0.0f;
#pragma unroll
            for (int c = 0; c < 16; c++) {
                float4 qv = qrow[c];
                a += qv.x * kv[c].x + qv.y * kv[c].y + qv.z * kv[c].z + qv.w * kv[c].w;
            }
            sc[u * SEQ + kt * 64 + key] = a * 0.125f;
        }
        __syncthreads();
    }

    for (int u = warp; u < nu; u += 8) {
        float m = -1e38f;
        for (int i = lane; i < SEQ; i += 32) m = fmaxf(m, sc[u * SEQ + i]);
#pragma unroll
        for (int o = 16; o; o >>= 1) m = fmaxf(m, __shfl_xor_sync(0xffffffffu, m, o));
        float s = 0.0f;
        for (int i = lane; i < SEQ; i += 32) {
            float e = expf(sc[u * SEQ + i] - m);
            sc[u * SEQ + i] = e;
            s += e;
        }
#pragma unroll
        for (int o = 16; o; o >>= 1) s += __shfl_xor_sync(0xffffffffu, s, o);
        if (lane == 0) rden[u] = 1.0f / s;
    }
    __syncthreads();

    for (int f = tid; f < nu * SEQ; f += 256) {
        int u = f >> 10;
        sc[f] = tf32r(sc[f] * rden[u]);
    }
    __syncthreads();

    const int d = key;
    float acc[5];
#pragma unroll
    for (int j = 0; j < 5; j++) acc[j] = 0.0f;

    for (int kt = 0; kt < 16; kt++) {
        for (int i = tid; i < 1024; i += 256) {
            int kr = i >> 4, d4 = i & 15;
            float4 vv = *(const float4*)&V[((size_t)(b * SEQ + kt * 64 + kr)) * DM + h * DK + d4 * 4];
            float* dst = &ks[kr * KSTR2 + d4 * 4];
            dst[0] = tf32r(vv.x); dst[1] = tf32r(vv.y);
            dst[2] = tf32r(vv.z); dst[3] = tf32r(vv.w);
        }
        __syncthreads();

#pragma unroll 4
        for (int kb = 0; kb < 64; kb += 4) {
            float v0 = ks[(kb + 0) * KSTR2 + d];
            float v1 = ks[(kb + 1) * KSTR2 + d];
            float v2 = ks[(kb + 2) * KSTR2 + d];
            float v3 = ks[(kb + 3) * KSTR2 + d];
            int j = 0;
            for (int u = ug; u < nu; u += 4, j++) {
                float4 s4 = *(const float4*)&sc[u * SEQ + kt * 64 + kb];
                acc[j] += s4.x * v0 + s4.y * v1 + s4.z * v2 + s4.w * v3;
            }
        }
        __syncthreads();
    }

    int j = 0;
    for (int u = ug; u < nu; u += 4, j++) {
        int qr = top[bh * NTOP + u0 + u];
        hctx[((size_t)(b * SEQ + qr)) * DM + h * DK + d] = __float2half_rn(acc[j]);
    }
}

// ---------------------------------------------------------------------------
// BatchNorm (atomic partials; measured-best config)
// ---------------------------------------------------------------------------
__global__ void bn_zero_kernel() {
    int i = blockIdx.x * 256 + threadIdx.x;
    if (i < DM) { g_bsum[i] = 0.0f; g_bsq[i] = 0.0f; }
}

__global__ void bn_partial_kernel(const float* __restrict__ x) {
    int blk = blockIdx.x;
    int tid = threadIdx.x;
    float s[4] = {0, 0, 0, 0}, q[4] = {0, 0, 0, 0};
    const float* base = x + (size_t)blk * 64 * DM;
    for (int r = 0; r < 64; r++) {
#pragma unroll
        for (int j = 0; j < 4; j++) {
            float v = base[(size_t)r * DM + tid + j * 256];
            s[j] += v; q[j] += v * v;
        }
    }
#pragma unroll
    for (int j = 0; j < 4; j++) {
        atomicAdd(&g_bsum[tid + j * 256], s[j]);
        atomicAdd(&g_bsq[tid + j * 256], q[j]);
    }
}

__global__ void bn_final_kernel(float* __restrict__ mu, float* __restrict__ rstd) {
    int c = blockIdx.x * 256 + threadIdx.x;
    if (c < DM) {
        float m = g_bsum[c] * (1.0f / (float)ROWS);
        float v = g_bsq[c] * (1.0f / (float)ROWS) - m * m;
        mu[c] = m;
        rstd[c] = rsqrtf(v + 1e-5f);
    }
}

__global__ void bn_apply4_kernel(const float* __restrict__ x, const float* __restrict__ mu,
                                 const float* __restrict__ rstd, const float* __restrict__ g,
                                 const float* __restrict__ bta, float* __restrict__ y,
                                 __half* __restrict__ yh) {
    size_t i = (size_t)blockIdx.x * 256 + threadIdx.x;
    int c4 = (int)(i & 255);
    float4 xv = ((const float4*)x)[i];
    float4 m = ((const float4*)mu)[c4];
    float4 r = ((const float4*)rstd)[c4];
    float4 gg = ((const float4*)g)[c4];
    float4 bb = ((const float4*)bta)[c4];
    float4 o;
    o.x = (xv.x - m.x) * r.x * gg.x + bb.x;
    o.y = (xv.y - m.y) * r.y * gg.y + bb.y;
    o.z = (xv.z - m.z) * r.z * gg.z + bb.z;
    o.w = (xv.w - m.w) * r.w * gg.w + bb.w;
    ((float4*)y)[i] = o;
    if (yh) {
        __half2 h0 = __floats2half2_rn(o.x, o.y);
        __half2 h1 = __floats2half2_rn(o.z, o.w);
        uint2 ho = { *(uint32_t*)&h0, *(uint32_t*)&h1 };
        ((uint2*)yh)[i] = ho;
    }
}

// ---------------------------------------------------------------------------
// Launch helpers
// ---------------------------------------------------------------------------
static void run_gemm(const __half* A, const __half* B, const float* bias,
                     const float* resid, float* C, __half* Ch,
                     int M, int N, int K, int act) {
    dim3 grid(N / 128, M / 128);
    gemm_h_kernel<<<grid, 256, H_SMEM>>>(A, B, bias, resid, C, Ch, M, N, K, act);
}

static void run_bn(const float* x, float* mu, float* rs,
                   const float* g, const float* bta, float* y, __half* yh) {
    bn_zero_kernel<<<4, 256>>>();
    bn_partial_kernel<<<64, 256>>>(x);
    bn_final_kernel<<<4, 256>>>(mu, rs);
    bn_apply4_kernel<<<(int)(NELEM / 4 / 256), 256>>>(x, mu, rs, g, bta, y, yh);
}

extern "C" void kernel_launch(void* const* d_in, const int* in_sizes, int n_in,
                              void* d_out, int out_size) {
    const float* tgt   = (const float*)d_in[0];
    const float* mem   = (const float*)d_in[1];
    const float* sa_wq = (const float*)d_in[2];
    const float* sa_bq = (const float*)d_in[3];
    const float* sa_wk = (const float*)d_in[4];
    const float* sa_bk = (const float*)d_in[5];
    const float* sa_wv = (const float*)d_in[6];
    const float* sa_bv = (const float*)d_in[7];
    const float* sa_wo = (const float*)d_in[8];
    const float* sa_bo = (const float*)d_in[9];
    const float* ca_wq = (const float*)d_in[10];
    const float* ca_bq = (const float*)d_in[11];
    const float* ca_wk = (const float*)d_in[12];
    const float* ca_bk = (const float*)d_in[13];
    const float* ca_wv = (const float*)d_in[14];
    const float* ca_bv = (const float*)d_in[15];
    const float* ca_wo = (const float*)d_in[16];
    const float* ca_bo = (const float*)d_in[17];
    const float* w1    = (const float*)d_in[18];
    const float* b1    = (const float*)d_in[19];
    const float* w2    = (const float*)d_in[20];
    const float* b2    = (const float*)d_in[21];
    const float* bn1_g = (const float*)d_in[22];
    const float* bn1_b = (const float*)d_in[23];
    const float* bn2_g = (const float*)d_in[24];
    const float* bn2_b = (const float*)d_in[25];
    const float* bn3_g = (const float*)d_in[26];
    const float* bn3_b = (const float*)d_in[27];
    float* out = (float*)d_out;

    cudaFuncSetAttribute(gemm_h_kernel, cudaFuncAttributeMaxDynamicSharedMemorySize, H_SMEM);
    cudaFuncSetAttribute(gemm_h_qkv_kernel, cudaFuncAttributeMaxDynamicSharedMemorySize, H_SMEM);
    cudaFuncSetAttribute(attn_bh_kernel, cudaFuncAttributeMaxDynamicSharedMemorySize, ATTN_SMEM);

    float *q, *k, *v, *xin, *x1, *x2, *Mb, *vm, *mu, *rs;
    int *top, *idx;
    __half *htgt, *hmem, *hx1, *hx2, *hctx, *hh, *hwq, *hwk, *hwv, *hwo, *hw1, *hw2;
    cudaGetSymbolAddress((void**)&q,    g_q);
    cudaGetSymbolAddress((void**)&k,    g_k);
    cudaGetSymbolAddress((void**)&v,    g_v);
    cudaGetSymbolAddress((void**)&xin,  g_xin);
    cudaGetSymbolAddress((void**)&x1,   g_x1);
    cudaGetSymbolAddress((void**)&x2,   g_x2);
    cudaGetSymbolAddress((void**)&Mb,   g_M);
    cudaGetSymbolAddress((void**)&vm,   g_vmean);
    cudaGetSymbolAddress((void**)&top,  g_top);
    cudaGetSymbolAddress((void**)&idx,  g_idx);
    cudaGetSymbolAddress((void**)&mu,   g_mu);
    cudaGetSymbolAddress((void**)&rs,   g_rstd);
    cudaGetSymbolAddress((void**)&htgt, g_htgt);
    cudaGetSymbolAddress((void**)&hmem, g_hmem);
    cudaGetSymbolAddress((void**)&hx1,  g_hx1);
    cudaGetSymbolAddress((void**)&hx2,  g_hx2);
    cudaGetSymbolAddress((void**)&hctx, g_hctx);
    cudaGetSymbolAddress((void**)&hh,   g_hh);
    cudaGetSymbolAddress((void**)&hwq,  g_hwq);
    cudaGetSymbolAddress((void**)&hwk,  g_hwk);
    cudaGetSymbolAddress((void**)&hwv,  g_hwv);
    cudaGetSymbolAddress((void**)&hwo,  g_hwo);
    cudaGetSymbolAddress((void**)&hw1,  g_hw1);
    cudaGetSymbolAddress((void**)&hw2,  g_hw2);

    // Key derivation (frozen): root=key(42); k1,k2=split(root); randint uses split(rng)[1]
    uint32_t r1a, r1b, r2a, r2b;
    uint32_t s1a, s1b, s2a, s2b;
#if RNG_PARTITIONABLE
    tf2x32(0u, 42u, 0u, 0u, r1a, r1b);
    tf2x32(0u, 42u, 0u, 1u, r2a, r2b);
    tf2x32(r1a, r1b, 0u, 1u, s1a, s1b);
    tf2x32(r2a, r2b, 0u, 1u, s2a, s2b);
#else
    {
        uint32_t a0, b0, a1, b1;
        tf2x32(0u, 42u, 0u, 2u, a0, b0);
        tf2x32(0u, 42u, 1u, 3u, a1, b1);
        r1a = a0; r1b = a1;
        r2a = b0; r2b = b1;
        tf2x32(r1a, r1b, 0u, 2u, a0, b0);
        tf2x32(r1a, r1b, 1u, 3u, a1, b1);
        s1a = b0; s1b = b1;
        tf2x32(r2a, r2b, 0u, 2u, a0, b0);
        tf2x32(r2a, r2b, 1u, 3u, a1, b1);
        s2a = b0; s2b = b1;
    }
#endif

    const int ELT4_BLKS = (int)(NELEM / 4 / 256);
    const int IDX_BLKS = (IDX_N + 255) / 256;
    const int M_BLKS = BATCH * NH * SEQ / 8;
    dim3 qkv_grid(DM / 128, ROWS / 128, 3);
    dim3 attn_grid(BATCH * NH, 2);

    // ================= Self-attention =================
    make_idx_kernel<<<IDX_BLKS, 256>>>(s1a, s1b, idx);
    run_f2h(tgt, htgt, NELEM);
    run_f2h(mem, hmem, NELEM);
    run_f2h(sa_wq, hwq, (size_t)DM * DM);
    run_f2h(sa_wk, hwk, (size_t)DM * DM);
    run_f2h(sa_wv, hwv, (size_t)DM * DM);
    run_f2h(sa_wo, hwo, (size_t)DM * DM);
    gemm_h_qkv_kernel<<<qkv_grid, 256, H_SMEM>>>(
        htgt, htgt, htgt, hwq, hwk, hwv, sa_bq, sa_bk, sa_bv,
        q, k, v, ROWS, DM, DM);
    compute_M_kernel<<<M_BLKS, 256>>>(q, k, idx, Mb);
    topk_kernel<<<BATCH * NH, 1024>>>(Mb, top);
    vmean_kernel<<<BATCH * NH, 256>>>(v, vm);
    fill_ctx4_kernel<<<ELT4_BLKS, 256>>>(vm, hctx);
    attn_bh_kernel<<<attn_grid, 256, ATTN_SMEM>>>(q, k, v, top, hctx);
    run_gemm(hctx, hwo, sa_bo, tgt, xin, nullptr, ROWS, DM, DM, 0);
    run_bn(xin, mu, rs, bn1_g, bn1_b, x1, hx1);

    // ================= Cross-attention =================
    make_idx_kernel<<<IDX_BLKS, 256>>>(s2a, s2b, idx);
    run_f2h(ca_wq, hwq, (size_t)DM * DM);
    run_f2h(ca_wk, hwk, (size_t)DM * DM);
    run_f2h(ca_wv, hwv, (size_t)DM * DM);
    run_f2h(ca_wo, hwo, (size_t)DM * DM);
    gemm_h_qkv_kernel<<<qkv_grid, 256, H_SMEM>>>(
        hx1, hmem, hmem, hwq, hwk, hwv, ca_bq, ca_bk, ca_bv,
        q, k, v, ROWS, DM, DM);
    compute_M_kernel<<<M_BLKS, 256>>>(q, k, idx, Mb);
    topk_kernel<<<BATCH * NH, 1024>>>(Mb, top);
    vmean_kernel<<<BATCH * NH, 256>>>(v, vm);
    fill_ctx4_kernel<<<ELT4_BLKS, 256>>>(vm, hctx);
    attn_bh_kernel<<<attn_grid, 256, ATTN_SMEM>>>(q, k, v, top, hctx);
    run_gemm(hctx, hwo, ca_bo, x1, xin, nullptr, ROWS, DM, DM, 0);
    run_bn(xin, mu, rs, bn2_g, bn2_b, x2, hx2);

    // ================= FFN =================
    run_f2h(w1, hw1, (size_t)DM * DFF);
    run_f2h(w2, hw2, (size_t)DM * DFF);
    run_gemm(hx2, hw1, b1, nullptr, nullptr, hh, ROWS, DFF, DM, 1);
    run_gemm(hh, hw2, b2, x2, xin, nullptr, ROWS, DM, DFF, 0);
    run_bn(xin, mu, rs, bn3_g, bn3_b, out, nullptr);
}